// round 13
// baseline (speedup 1.0000x reference)
#include <cuda_runtime.h>
#include <cuda_fp16.h>
#include <cstdint>

// LoLa: out[m,0]=rowsum(x); out[m,1:513]=x; out[m,513:1025]=x@w
// R11 GEMM core (fp16 HMMA, KT=64, 3-stage ring, ldmatrix, 2 CTAs/SM) +
// in-kernel producer CTAs (nb==0, lowest bid per group): read x fp32 once,
// write copy cols + rowsum + fp16-converted A tile, then release flag.
// GEMM CTAs (nb 1..4) spin on flag, then run the proven mainloop.

#define M_TOTAL   131072
#define KDIM      512
#define NOUT      512
#define OUT_COLS  1025

#define MT 128
#define NT 128
#define KT 64
#define KW (KT / 2)            // 32 half2 words per tile
#define NKT (KDIM / KT)        // 8
#define NSTAGE 3
#define NMB (M_TOTAL / MT)     // 1024

#define SWW(r, c) ((r) * 32 + ((c) ^ (((r) & 7) << 2)))

#define XS_WORDS  (MT * 32)                    // 4096
#define WS_WORDS  (NT * 32)                    // 4096
#define STAGE_WORDS (XS_WORDS + WS_WORDS)      // 8192
#define SMEM_TOTAL  (NSTAGE * STAGE_WORDS * 4) // 98304 B -> 2 CTAs/SM

__device__ uint32_t g_x_f16[M_TOTAL * KDIM / 2];   // [m][k/2] packed half2
__device__ uint32_t g_wT_f16[NOUT * KDIM / 2];     // [n][k/2] (transposed)
__device__ unsigned g_flag[NMB];                   // per-m-tile ready flag

__device__ __forceinline__ uint32_t packh2(float lo, float hi) {
    __half2 h = __floats2half2_rn(lo, hi);
    return *(uint32_t*)&h;
}
__device__ __forceinline__ void cp_async16(uint32_t saddr, const void* g) {
    asm volatile("cp.async.cg.shared.global [%0], [%1], 16;" :: "r"(saddr), "l"(g));
}
__device__ __forceinline__ void cp_commit() {
    asm volatile("cp.async.commit_group;" ::);
}
template <int N> __device__ __forceinline__ void cp_wait() {
    asm volatile("cp.async.wait_group %0;" :: "n"(N));
}
__device__ __forceinline__ void ldsm_x4(uint32_t& r0, uint32_t& r1,
                                        uint32_t& r2, uint32_t& r3, uint32_t addr) {
    asm volatile("ldmatrix.sync.aligned.m8n8.x4.shared.b16 {%0,%1,%2,%3}, [%4];"
                 : "=r"(r0), "=r"(r1), "=r"(r2), "=r"(r3) : "r"(addr));
}

// g_wT[n*256 + kp] = (w[2kp][n], w[2kp+1][n])
__global__ void w_convert_kernel(const float* __restrict__ w) {
    int idx = blockIdx.x * 256 + threadIdx.x;     // 0..131071
    int n = idx >> 8, kp = idx & 255;
    g_wT_f16[idx] = packh2(w[(size_t)(2 * kp) * NOUT + n],
                           w[(size_t)(2 * kp + 1) * NOUT + n]);
}

__global__ void flag_reset_kernel() {
    g_flag[blockIdx.x * 256 + threadIdx.x] = 0u;
}

__global__ __launch_bounds__(256, 2)
void lola_fused_kernel(const float* __restrict__ x,
                       float* __restrict__ out)
{
    extern __shared__ uint32_t smem[];

    const int nb   = blockIdx.x;              // 0 = producer, 1..4 = GEMM
    const int mb   = blockIdx.y;              // 0..1023
    const int m0   = mb * MT;
    const int tid  = threadIdx.x;
    const int lane = tid & 31;
    const int warp = tid >> 5;

    // ========== producer CTA: copy + rowsum + fp16 convert, then flag ==========
    if (nb == 0) {
        #pragma unroll 1
        for (int rr = 0; rr < 16; rr++) {
            const int r = m0 + warp + rr * 8;
            const float4* xr = (const float4*)&x[(size_t)r * KDIM];
            float* orow = &out[(size_t)r * OUT_COLS];
            uint32_t* frow = &g_x_f16[(size_t)r * (KDIM / 2)];
            float s = 0.f;
            #pragma unroll
            for (int j = 0; j < 4; j++) {
                float4 v = xr[lane + 32 * j];
                s += (v.x + v.y) + (v.z + v.w);
                float* o = &orow[1 + (lane + 32 * j) * 4];
                o[0] = v.x; o[1] = v.y; o[2] = v.z; o[3] = v.w;
                uint2 p;
                p.x = packh2(v.x, v.y);
                p.y = packh2(v.z, v.w);
                *(uint2*)&frow[(lane + 32 * j) * 2] = p;
            }
            s += __shfl_xor_sync(0xffffffffu, s, 16);
            s += __shfl_xor_sync(0xffffffffu, s, 8);
            s += __shfl_xor_sync(0xffffffffu, s, 4);
            s += __shfl_xor_sync(0xffffffffu, s, 2);
            s += __shfl_xor_sync(0xffffffffu, s, 1);
            if (lane == 0) orow[0] = s;
        }
        __threadfence();
        __syncthreads();
        if (tid == 0) atomicExch(&g_flag[mb], 1u);
        return;
    }

    // ========== GEMM CTAs ==========
    // wait for this m-tile's fp16 data (producer has strictly lower bid)
    if (tid == 0) {
        while (atomicAdd(&g_flag[mb], 0u) == 0u) __nanosleep(64);
    }
    __syncthreads();

    const int n0 = (nb - 1) * NT;
    const int warp_m = warp & 1;              // m offset *64
    const int warp_n = warp >> 1;             // n offset *32
    const uint32_t smem_base = (uint32_t)__cvta_generic_to_shared(smem);

    float acc[4][4][4];                       // warp tile 64x32
    #pragma unroll
    for (int i = 0; i < 4; i++)
        #pragma unroll
        for (int j = 0; j < 4; j++)
            #pragma unroll
            for (int k = 0; k < 4; k++)
                acc[i][j][k] = 0.0f;

    auto stage = [&](int kt) {
        const int s   = kt % NSTAGE;
        const int kw0 = kt * KW;
        uint32_t xb = smem_base + s * STAGE_WORDS * 4;
        uint32_t wb = xb + XS_WORDS * 4;
        #pragma unroll
        for (int i = 0; i < 4; i++) {          // A: 128 rows x 32 words
            int idx = tid + i * 256;
            int r = idx >> 3, c = (idx & 7) * 4;
            cp_async16(xb + SWW(r, c) * 4,
                       &g_x_f16[(size_t)(m0 + r) * (KDIM / 2) + kw0 + c]);
        }
        #pragma unroll
        for (int i = 0; i < 4; i++) {          // B^T: 128 n-rows x 32 words
            int idx = tid + i * 256;
            int r = idx >> 3, c = (idx & 7) * 4;
            cp_async16(wb + SWW(r, c) * 4,
                       &g_wT_f16[(size_t)(n0 + r) * (KDIM / 2) + kw0 + c]);
        }
        cp_commit();
    };

    stage(0); stage(1);

    const int a_row_l = warp_m * 64 + (lane & 15);
    const int a_chunk = (lane >> 4) * 4;
    const int b_row_l = warp_n * 32 + (lane & 7) + ((lane >> 4) << 3);
    const int b_chunk = ((lane >> 3) & 1) * 4;

    #pragma unroll 1
    for (int kt = 0; kt < NKT; kt++) {
        const int s = kt % NSTAGE;
        const uint32_t xa = smem_base + s * STAGE_WORDS * 4;
        const uint32_t wa = xa + XS_WORDS * 4;

        if (kt + 2 < NKT) cp_wait<1>(); else cp_wait<0>();
        __syncthreads();

        uint32_t afrag[2][4][4];
        #pragma unroll
        for (int mf = 0; mf < 4; mf++) {
            int r = a_row_l + mf * 16;
            ldsm_x4(afrag[0][mf][0], afrag[0][mf][1], afrag[0][mf][2], afrag[0][mf][3],
                    xa + SWW(r, a_chunk) * 4);
        }

        if (kt + 2 < NKT) stage(kt + 2);

        #pragma unroll
        for (int j = 0; j < 4; j++) {
            const int kk  = j * 8;
            const int cur = j & 1;
            uint32_t bfrag[4][2];
            #pragma unroll
            for (int g = 0; g < 2; g++) {
                int r = b_row_l + g * 16;
                ldsm_x4(bfrag[2 * g][0], bfrag[2 * g][1],
                        bfrag[2 * g + 1][0], bfrag[2 * g + 1][1],
                        wa + SWW(r, kk + b_chunk) * 4);
            }
            if (j < 3) {
                #pragma unroll
                for (int mf = 0; mf < 4; mf++) {
                    int r = a_row_l + mf * 16;
                    ldsm_x4(afrag[cur ^ 1][mf][0], afrag[cur ^ 1][mf][1],
                            afrag[cur ^ 1][mf][2], afrag[cur ^ 1][mf][3],
                            xa + SWW(r, kk + 8 + a_chunk) * 4);
                }
            }
            #pragma unroll
            for (int mf = 0; mf < 4; mf++) {
                #pragma unroll
                for (int nf = 0; nf < 4; nf++) {
                    asm volatile(
                        "mma.sync.aligned.m16n8k16.row.col.f32.f16.f16.f32 "
                        "{%0,%1,%2,%3}, {%4,%5,%6,%7}, {%8,%9}, {%0,%1,%2,%3};"
                        : "+f"(acc[mf][nf][0]), "+f"(acc[mf][nf][1]),
                          "+f"(acc[mf][nf][2]), "+f"(acc[mf][nf][3])
                        : "r"(afrag[cur][mf][0]), "r"(afrag[cur][mf][1]),
                          "r"(afrag[cur][mf][2]), "r"(afrag[cur][mf][3]),
                          "r"(bfrag[nf][0]), "r"(bfrag[nf][1]));
                }
            }
        }
    }

    // ---- epilogue: GEMM columns ----
    #pragma unroll
    for (int mf = 0; mf < 4; mf++) {
        int row = m0 + warp_m * 64 + mf * 16 + (lane >> 2);
        #pragma unroll
        for (int nf = 0; nf < 4; nf++) {
            int col = 513 + n0 + warp_n * 32 + nf * 8 + (lane & 3) * 2;
            out[(size_t)row * OUT_COLS + col]           = acc[mf][nf][0];
            out[(size_t)row * OUT_COLS + col + 1]       = acc[mf][nf][1];
            out[(size_t)(row + 8) * OUT_COLS + col]     = acc[mf][nf][2];
            out[(size_t)(row + 8) * OUT_COLS + col + 1] = acc[mf][nf][3];
        }
    }
}

extern "C" void kernel_launch(void* const* d_in, const int* in_sizes, int n_in,
                              void* d_out, int out_size)
{
    const float* x = (const float*)d_in[0];   // (131072, 512)
    const float* w = (const float*)d_in[1];   // (512, 512)
    float* out = (float*)d_out;               // (131072, 1025)

    w_convert_kernel<<<512, 256>>>(w);
    cudaFuncSetAttribute(lola_fused_kernel,
                         cudaFuncAttributeMaxDynamicSharedMemorySize, SMEM_TOTAL);
    dim3 grid(5, NMB);                        // nb0 producer + nb1..4 GEMM
    lola_fused_kernel<<<grid, 256, SMEM_TOTAL>>>(x, out);
    flag_reset_kernel<<<NMB / 256, 256>>>();  // leave flags 0 for next replay
}

// round 15
// speedup vs baseline: 1.4508x; 1.4508x over previous
#include <cuda_runtime.h>
#include <cuda_fp16.h>
#include <cstdint>

// LoLa: out[m,0]=rowsum(x); out[m,1:513]=x; out[m,513:1025]=x@w
// R11 core: fp16 m16n8k16 HMMA (fp32 acc), ldmatrix frags, XOR-swizzled SMEM,
// GEMM CTAs 128x128, KT=64, 3-stage cp.async ring, 1 barrier/ktile, 2 CTAs/SM.
// R15: scalar evict-first (.cs) stores for all `out` traffic (OUT_COLS=1025 is
// odd -> vector stores are misaligned), fully unrolled mainloop.

#define M_TOTAL   131072
#define KDIM      512
#define NOUT      512
#define OUT_COLS  1025

#define MT 128
#define NT 128
#define KT 64
#define KW (KT / 2)            // 32 half2 words per tile
#define NKT (KDIM / KT)        // 8
#define NSTAGE 3

#define SWW(r, c) ((r) * 32 + ((c) ^ (((r) & 7) << 2)))

#define XS_WORDS  (MT * 32)                    // 4096
#define WS_WORDS  (NT * 32)                    // 4096
#define STAGE_WORDS (XS_WORDS + WS_WORDS)      // 8192
#define SMEM_TOTAL  (NSTAGE * STAGE_WORDS * 4) // 98304 B -> 2 CTAs/SM

__device__ uint32_t g_x_f16[M_TOTAL * KDIM / 2];   // [m][k/2] packed half2
__device__ uint32_t g_wT_f16[NOUT * KDIM / 2];     // [n][k/2] (transposed)

__device__ __forceinline__ uint32_t packh2(float lo, float hi) {
    __half2 h = __floats2half2_rn(lo, hi);
    return *(uint32_t*)&h;
}
__device__ __forceinline__ void cp_async16(uint32_t saddr, const void* g) {
    asm volatile("cp.async.cg.shared.global [%0], [%1], 16;" :: "r"(saddr), "l"(g));
}
__device__ __forceinline__ void cp_commit() {
    asm volatile("cp.async.commit_group;" ::);
}
template <int N> __device__ __forceinline__ void cp_wait() {
    asm volatile("cp.async.wait_group %0;" :: "n"(N));
}
__device__ __forceinline__ void ldsm_x4(uint32_t& r0, uint32_t& r1,
                                        uint32_t& r2, uint32_t& r3, uint32_t addr) {
    asm volatile("ldmatrix.sync.aligned.m8n8.x4.shared.b16 {%0,%1,%2,%3}, [%4];"
                 : "=r"(r0), "=r"(r1), "=r"(r2), "=r"(r3) : "r"(addr));
}
__device__ __forceinline__ void stg_cs_f32(float* p, float v) {
    asm volatile("st.global.cs.f32 [%0], %1;" :: "l"(p), "f"(v) : "memory");
}

__global__ void x_convert_kernel(const float* __restrict__ x) {
    size_t i = ((size_t)blockIdx.x * 256 + threadIdx.x) * 8;
    float4 a = *(const float4*)&x[i];
    float4 b = *(const float4*)&x[i + 4];
    uint4 o;
    o.x = packh2(a.x, a.y); o.y = packh2(a.z, a.w);
    o.z = packh2(b.x, b.y); o.w = packh2(b.z, b.w);
    *(uint4*)&g_x_f16[i / 2] = o;
}

// g_wT[n*256 + kp] = (w[2kp][n], w[2kp+1][n])
__global__ void w_convert_kernel(const float* __restrict__ w) {
    int idx = blockIdx.x * 256 + threadIdx.x;     // 0..131071
    int n = idx >> 8, kp = idx & 255;
    g_wT_f16[idx] = packh2(w[(size_t)(2 * kp) * NOUT + n],
                           w[(size_t)(2 * kp + 1) * NOUT + n]);
}

__global__ __launch_bounds__(256, 2)
void lola_fused_kernel(const float* __restrict__ x,
                       float* __restrict__ out)
{
    extern __shared__ uint32_t smem[];

    const int nb   = blockIdx.x;              // 0..4
    const int mb   = blockIdx.y;              // 0..1023
    const int m0   = mb * MT;
    const int tid  = threadIdx.x;
    const int lane = tid & 31;
    const int warp = tid >> 5;

    // ================= copy + rowsum CTAs =================
    if (nb == 4) {
        #pragma unroll 1
        for (int rr = 0; rr < 16; rr++) {
            const int r = m0 + warp + rr * 8;
            const float4* xr = (const float4*)&x[(size_t)r * KDIM];
            float* orow = &out[(size_t)r * OUT_COLS];
            float s = 0.f;
            #pragma unroll
            for (int j = 0; j < 4; j++) {
                float4 v = xr[lane + 32 * j];
                s += (v.x + v.y) + (v.z + v.w);
                float* o = &orow[1 + (lane + 32 * j) * 4];
                stg_cs_f32(o + 0, v.x);
                stg_cs_f32(o + 1, v.y);
                stg_cs_f32(o + 2, v.z);
                stg_cs_f32(o + 3, v.w);
            }
            s += __shfl_xor_sync(0xffffffffu, s, 16);
            s += __shfl_xor_sync(0xffffffffu, s, 8);
            s += __shfl_xor_sync(0xffffffffu, s, 4);
            s += __shfl_xor_sync(0xffffffffu, s, 2);
            s += __shfl_xor_sync(0xffffffffu, s, 1);
            if (lane == 0) stg_cs_f32(&orow[0], s);
        }
        return;
    }

    // ================= GEMM CTAs =================
    const int n0 = nb * NT;
    const int warp_m = warp & 1;              // m offset *64
    const int warp_n = warp >> 1;             // n offset *32
    const uint32_t smem_base = (uint32_t)__cvta_generic_to_shared(smem);

    float acc[4][4][4];                       // warp tile 64x32
    #pragma unroll
    for (int i = 0; i < 4; i++)
        #pragma unroll
        for (int j = 0; j < 4; j++)
            #pragma unroll
            for (int k = 0; k < 4; k++)
                acc[i][j][k] = 0.0f;

    auto stage = [&](int kt) {
        const int s   = kt % NSTAGE;
        const int kw0 = kt * KW;
        uint32_t xb = smem_base + s * STAGE_WORDS * 4;
        uint32_t wb = xb + XS_WORDS * 4;
        #pragma unroll
        for (int i = 0; i < 4; i++) {          // A: 128 rows x 32 words
            int idx = tid + i * 256;
            int r = idx >> 3, c = (idx & 7) * 4;
            cp_async16(xb + SWW(r, c) * 4,
                       &g_x_f16[(size_t)(m0 + r) * (KDIM / 2) + kw0 + c]);
        }
        #pragma unroll
        for (int i = 0; i < 4; i++) {          // B^T: 128 n-rows x 32 words
            int idx = tid + i * 256;
            int r = idx >> 3, c = (idx & 7) * 4;
            cp_async16(wb + SWW(r, c) * 4,
                       &g_wT_f16[(size_t)(n0 + r) * (KDIM / 2) + kw0 + c]);
        }
        cp_commit();
    };

    stage(0); stage(1);

    const int a_row_l = warp_m * 64 + (lane & 15);
    const int a_chunk = (lane >> 4) * 4;
    const int b_row_l = warp_n * 32 + (lane & 7) + ((lane >> 4) << 3);
    const int b_chunk = ((lane >> 3) & 1) * 4;

    #pragma unroll
    for (int kt = 0; kt < NKT; kt++) {
        const int s = kt % NSTAGE;
        const uint32_t xa = smem_base + s * STAGE_WORDS * 4;
        const uint32_t wa = xa + XS_WORDS * 4;

        if (kt + 2 < NKT) cp_wait<1>(); else cp_wait<0>();
        __syncthreads();   // stage kt visible; slot (kt+2)%3 free

        uint32_t afrag[2][4][4];
        #pragma unroll
        for (int mf = 0; mf < 4; mf++) {
            int r = a_row_l + mf * 16;
            ldsm_x4(afrag[0][mf][0], afrag[0][mf][1], afrag[0][mf][2], afrag[0][mf][3],
                    xa + SWW(r, a_chunk) * 4);
        }

        if (kt + 2 < NKT) stage(kt + 2);       // cp.async issue covers LDSM latency

        #pragma unroll
        for (int j = 0; j < 4; j++) {
            const int kk  = j * 8;
            const int cur = j & 1;
            uint32_t bfrag[4][2];
            #pragma unroll
            for (int g = 0; g < 2; g++) {
                int r = b_row_l + g * 16;
                ldsm_x4(bfrag[2 * g][0], bfrag[2 * g][1],
                        bfrag[2 * g + 1][0], bfrag[2 * g + 1][1],
                        wa + SWW(r, kk + b_chunk) * 4);
            }
            if (j < 3) {
                #pragma unroll
                for (int mf = 0; mf < 4; mf++) {
                    int r = a_row_l + mf * 16;
                    ldsm_x4(afrag[cur ^ 1][mf][0], afrag[cur ^ 1][mf][1],
                            afrag[cur ^ 1][mf][2], afrag[cur ^ 1][mf][3],
                            xa + SWW(r, kk + 8 + a_chunk) * 4);
                }
            }
            #pragma unroll
            for (int mf = 0; mf < 4; mf++) {
                #pragma unroll
                for (int nf = 0; nf < 4; nf++) {
                    asm volatile(
                        "mma.sync.aligned.m16n8k16.row.col.f32.f16.f16.f32 "
                        "{%0,%1,%2,%3}, {%4,%5,%6,%7}, {%8,%9}, {%0,%1,%2,%3};"
                        : "+f"(acc[mf][nf][0]), "+f"(acc[mf][nf][1]),
                          "+f"(acc[mf][nf][2]), "+f"(acc[mf][nf][3])
                        : "r"(afrag[cur][mf][0]), "r"(afrag[cur][mf][1]),
                          "r"(afrag[cur][mf][2]), "r"(afrag[cur][mf][3]),
                          "r"(bfrag[nf][0]), "r"(bfrag[nf][1]));
                }
            }
        }
    }

    // ---- epilogue: GEMM columns, scalar streaming stores ----
    #pragma unroll
    for (int mf = 0; mf < 4; mf++) {
        int row = m0 + warp_m * 64 + mf * 16 + (lane >> 2);
        #pragma unroll
        for (int nf = 0; nf < 4; nf++) {
            int col = 513 + n0 + warp_n * 32 + nf * 8 + (lane & 3) * 2;
            stg_cs_f32(&out[(size_t)row * OUT_COLS + col],           acc[mf][nf][0]);
            stg_cs_f32(&out[(size_t)row * OUT_COLS + col + 1],       acc[mf][nf][1]);
            stg_cs_f32(&out[(size_t)(row + 8) * OUT_COLS + col],     acc[mf][nf][2]);
            stg_cs_f32(&out[(size_t)(row + 8) * OUT_COLS + col + 1], acc[mf][nf][3]);
        }
    }
}

extern "C" void kernel_launch(void* const* d_in, const int* in_sizes, int n_in,
                              void* d_out, int out_size)
{
    const float* x = (const float*)d_in[0];   // (131072, 512)
    const float* w = (const float*)d_in[1];   // (512, 512)
    float* out = (float*)d_out;               // (131072, 1025)

    w_convert_kernel<<<512, 256>>>(w);
    x_convert_kernel<<<32768, 256>>>(x);
    cudaFuncSetAttribute(lola_fused_kernel,
                         cudaFuncAttributeMaxDynamicSharedMemorySize, SMEM_TOTAL);
    dim3 grid(5, M_TOTAL / MT);               // (4 GEMM + 1 copy, 1024)
    lola_fused_kernel<<<grid, 256, SMEM_TOTAL>>>(x, out);
}